// round 11
// baseline (speedup 1.0000x reference)
#include <cuda_runtime.h>
#include <cuda_bf16.h>
#include <math.h>

// Problem constants
#define B   256
#define S   512
#define D   768
#define D4  (D/4)        // 192 float4 per row
#define K4D 3072         // 4*D
#define H1  256
#define H2  64
#define L   4

// GEMM1 tiling
#define BM  32
#define BN  64
#define BK  32
#define KS  16
#define KC  (K4D/KS)     // 192 k per split
#define NT  (KC/BK)      // 6 k-tiles per block
#define FS  68           // padded fsh2 row stride (floats), 16B-aligned

// Scratch (device globals — no allocation allowed)
__device__ float g_f[B * K4D];            // features [256, 3072]  (3 MB)
__device__ float g_h1p[KS * B * H1];      // GEMM1 partials [16, 256, 256] (4 MB)

#define FFMA2(d, a, b) \
    asm("fma.rn.f32x2 %0, %1, %2, %0;" : "+l"(d) : "l"(a), "l"(b))

// ---------------------------------------------------------------------------
// K1: feature extraction. grid (B, 2) — blockIdx.y selects x1/x2.
// 768 threads: col = t%192 (float4 lane), rg = t/192 (4-way row split).
// Span: 8 fully-unrolled predicated loads (span<=32 -> rowgroup covers <=8
// rows) — all independent, front-batched by ptxas for max MLP.
// ---------------------------------------------------------------------------
__global__ void __launch_bounds__(768) feat_kernel(
    const float* __restrict__ x1, const float* __restrict__ x2,
    const int* __restrict__ s1a, const int* __restrict__ e1a,
    const int* __restrict__ s2a, const int* __restrict__ e2a)
{
    __shared__ float4 part[4][D4];        // 12 KB

    const int b   = blockIdx.x;
    const int sel = blockIdx.y;
    const int t   = threadIdx.x;
    const int col = t % D4;
    const int rg  = t / D4;

    const float* x = sel ? x2 : x1;
    int s = sel ? s2a[b] : s1a[b];
    int e = sel ? e2a[b] : e1a[b];
    e = max(e, s + 1);
    int lo = max(s, 0), hi = min(e, S);
    int cnt = max(hi - lo, 1);
    float inv = 1.0f / (float)cnt;

    const float4* x4 = reinterpret_cast<const float4*>(x);
    float4* f4 = reinterpret_cast<float4*>(g_f);
    const long base = (long)b * S * D4;
    const long frow = (long)b * (K4D / 4) + sel * (2 * D4);

    // CLS copy (rowgroup 0)
    if (rg == 0)
        f4[frow + col] = x4[base + col];

    // span partial sums: rows lo+rg+4j, j=0..7, predicated — no loop
    float4 acc = make_float4(0.f, 0.f, 0.f, 0.f);
    const int r0 = lo + rg;
    #pragma unroll
    for (int j = 0; j < 8; ++j) {
        int rr = r0 + 4 * j;
        if (rr < hi) {
            float4 v = x4[base + (long)rr * D4 + col];
            acc.x += v.x; acc.y += v.y; acc.z += v.z; acc.w += v.w;
        }
    }
    part[rg][col] = acc;
    __syncthreads();

    if (t < D4) {
        float4 a0 = part[0][t], a1 = part[1][t], a2 = part[2][t], a3 = part[3][t];
        float4 o;
        o.x = (a0.x + a1.x + a2.x + a3.x) * inv;
        o.y = (a0.y + a1.y + a2.y + a3.y) * inv;
        o.z = (a0.z + a1.z + a2.z + a3.z) * inv;
        o.w = (a0.w + a1.w + a2.w + a3.w) * inv;
        f4[frow + D4 + t] = o;
    }
}

// ---------------------------------------------------------------------------
// K2: GEMM1 split-K16, 32x64 tile, 4x4 micro-tile, packed f32x2 FMA,
// DOUBLE-BUFFERED smem tiles: next tile's LDGs issue before the FMA loop,
// STS lands in the alternate buffer, one barrier per tile.
// grid (B/BM=8, H1/BN=4, KS=16) = 512 blocks, 128 threads.
// ---------------------------------------------------------------------------
__global__ void __launch_bounds__(128) gemm1_kernel(
    const float* __restrict__ W1, const float* __restrict__ b1)
{
    __shared__ float fsh2[2][BK][FS];     // duplicated f tile x2: 17 KB
    __shared__ float wsh[2][BK][BN];      // w tile x2: 16 KB

    const int m0 = blockIdx.x * BM;
    const int n0 = blockIdx.y * BN;
    const int kz = blockIdx.z;
    const int k0 = kz * KC;

    const int tid = threadIdx.x;
    const int tx = tid % 16;              // col group: 4 cols each -> 64
    const int ty = tid / 16;              // row group: 4 rows each -> 32

    const float4* gf4 = reinterpret_cast<const float4*>(g_f);
    const float4* w4  = reinterpret_cast<const float4*>(W1);

    const int kq   = tid % 8;
    const int mrow = tid / 8;
    const int nq  = tid % 16;
    const int kr0 = tid / 16;

    unsigned long long acc2[4][2];
    #pragma unroll
    for (int r = 0; r < 4; ++r) { acc2[r][0] = 0ull; acc2[r][1] = 0ull; }

    float4 fv[2];
    float4 wv[4];

    // ---- prologue: load + stage tile 0 ----
    #pragma unroll
    for (int i = 0; i < 2; ++i) {
        int m = mrow + i * 16;
        fv[i] = gf4[(long)(m0 + m) * (K4D / 4) + k0 / 4 + kq];
    }
    #pragma unroll
    for (int i = 0; i < 4; ++i) {
        int kr = kr0 + i * 8;
        wv[i] = w4[(long)(k0 + kr) * (H1 / 4) + n0 / 4 + nq];
    }
    #pragma unroll
    for (int i = 0; i < 2; ++i) {
        int m = mrow + i * 16;
        *reinterpret_cast<float2*>(&fsh2[0][kq * 4 + 0][2 * m]) = make_float2(fv[i].x, fv[i].x);
        *reinterpret_cast<float2*>(&fsh2[0][kq * 4 + 1][2 * m]) = make_float2(fv[i].y, fv[i].y);
        *reinterpret_cast<float2*>(&fsh2[0][kq * 4 + 2][2 * m]) = make_float2(fv[i].z, fv[i].z);
        *reinterpret_cast<float2*>(&fsh2[0][kq * 4 + 3][2 * m]) = make_float2(fv[i].w, fv[i].w);
    }
    #pragma unroll
    for (int i = 0; i < 4; ++i) {
        int kr = kr0 + i * 8;
        *reinterpret_cast<float4*>(&wsh[0][kr][nq * 4]) = wv[i];
    }
    __syncthreads();

    // ---- main loop over NT k-tiles ----
    #pragma unroll
    for (int kt = 0; kt < NT; ++kt) {
        const int cur = kt & 1;
        const int nxt = cur ^ 1;

        // prefetch tile kt+1 into registers (overlaps the FMA loop below)
        if (kt + 1 < NT) {
            int kb = k0 + (kt + 1) * BK;
            #pragma unroll
            for (int i = 0; i < 2; ++i) {
                int m = mrow + i * 16;
                fv[i] = gf4[(long)(m0 + m) * (K4D / 4) + kb / 4 + kq];
            }
            #pragma unroll
            for (int i = 0; i < 4; ++i) {
                int kr = kr0 + i * 8;
                wv[i] = w4[(long)(kb + kr) * (H1 / 4) + n0 / 4 + nq];
            }
        }

        // FMA over current tile
        #pragma unroll
        for (int k = 0; k < BK; ++k) {
            const ulonglong2* fp =
                reinterpret_cast<const ulonglong2*>(&fsh2[cur][k][2 * (ty * 4)]);
            ulonglong2 fa = fp[0];
            ulonglong2 fb = fp[1];
            ulonglong2 wp = *reinterpret_cast<const ulonglong2*>(&wsh[cur][k][tx * 4]);
            FFMA2(acc2[0][0], fa.x, wp.x);  FFMA2(acc2[0][1], fa.x, wp.y);
            FFMA2(acc2[1][0], fa.y, wp.x);  FFMA2(acc2[1][1], fa.y, wp.y);
            FFMA2(acc2[2][0], fb.x, wp.x);  FFMA2(acc2[2][1], fb.x, wp.y);
            FFMA2(acc2[3][0], fb.y, wp.x);  FFMA2(acc2[3][1], fb.y, wp.y);
        }

        // stage tile kt+1 into the other buffer, single barrier
        if (kt + 1 < NT) {
            #pragma unroll
            for (int i = 0; i < 2; ++i) {
                int m = mrow + i * 16;
                *reinterpret_cast<float2*>(&fsh2[nxt][kq * 4 + 0][2 * m]) = make_float2(fv[i].x, fv[i].x);
                *reinterpret_cast<float2*>(&fsh2[nxt][kq * 4 + 1][2 * m]) = make_float2(fv[i].y, fv[i].y);
                *reinterpret_cast<float2*>(&fsh2[nxt][kq * 4 + 2][2 * m]) = make_float2(fv[i].z, fv[i].z);
                *reinterpret_cast<float2*>(&fsh2[nxt][kq * 4 + 3][2 * m]) = make_float2(fv[i].w, fv[i].w);
            }
            #pragma unroll
            for (int i = 0; i < 4; ++i) {
                int kr = kr0 + i * 8;
                *reinterpret_cast<float4*>(&wsh[nxt][kr][nq * 4]) = wv[i];
            }
            __syncthreads();
        }
    }

    // epilogue: unpack, fold bias into split 0, store partials
    float* outp = g_h1p + (long)kz * (B * H1);
    #pragma unroll
    for (int r = 0; r < 4; ++r) {
        int m = m0 + ty * 4 + r;
        #pragma unroll
        for (int p = 0; p < 2; ++p) {
            int n = n0 + tx * 4 + p * 2;
            float lo = __uint_as_float((unsigned)(acc2[r][p] & 0xffffffffull));
            float hi = __uint_as_float((unsigned)(acc2[r][p] >> 32));
            if (kz == 0) { lo += b1[n]; hi += b1[n + 1]; }
            outp[(long)m * H1 + n]     = lo;
            outp[(long)m * H1 + n + 1] = hi;
        }
    }
}

// ---------------------------------------------------------------------------
// K3: per-batch fused tail: reduce split-K partials + ReLU -> GEMM2 + ReLU ->
// GEMM3 -> softmax. One block per batch sample, 256 threads.
// ---------------------------------------------------------------------------
__global__ void __launch_bounds__(H1) tail_kernel(
    const float* __restrict__ W2, const float* __restrict__ b2,
    const float* __restrict__ W3, const float* __restrict__ b3,
    float* __restrict__ out)
{
    __shared__ float hsh[H1];
    __shared__ float p2sh[4][H2];
    __shared__ float h2sh[H2];
    __shared__ float lsh[L];

    const int b = blockIdx.x;
    const int t = threadIdx.x;

    // reduce split-K partials + ReLU
    {
        float v = 0.f;
        #pragma unroll
        for (int p = 0; p < KS; ++p)
            v += g_h1p[(long)p * (B * H1) + (long)b * H1 + t];
        hsh[t] = fmaxf(v, 0.f);
    }
    __syncthreads();

    // GEMM2: 4-way k split, all 256 threads active
    {
        const int j  = t % H2;
        const int kg = t / H2;
        float acc = 0.f;
        #pragma unroll 8
        for (int k = kg * 64; k < (kg + 1) * 64; ++k)
            acc = fmaf(hsh[k], W2[k * H2 + j], acc);
        p2sh[kg][j] = acc;
    }
    __syncthreads();

    if (t < H2) {
        float acc = b2[t] + p2sh[0][t] + p2sh[1][t] + p2sh[2][t] + p2sh[3][t];
        h2sh[t] = fmaxf(acc, 0.f);
    }
    __syncthreads();

    // GEMM3 (tiny: 4 outputs x 64 k)
    if (t < L) {
        float acc = b3[t];
        #pragma unroll
        for (int k = 0; k < H2; ++k)
            acc = fmaf(h2sh[k], W3[k * L + t], acc);
        lsh[t] = acc;
    }
    __syncthreads();

    // softmax over L=4 (each of 4 threads recomputes — deterministic)
    if (t < L) {
        float mx = lsh[0];
        #pragma unroll
        for (int l = 1; l < L; ++l) mx = fmaxf(mx, lsh[l]);
        float s = 0.f;
        #pragma unroll
        for (int l = 0; l < L; ++l) s += expf(lsh[l] - mx);
        out[b * L + t] = expf(lsh[t] - mx) / s;
    }
}

// ---------------------------------------------------------------------------
extern "C" void kernel_launch(void* const* d_in, const int* in_sizes, int n_in,
                              void* d_out, int out_size)
{
    const float* x1 = (const float*)d_in[0];
    const float* x2 = (const float*)d_in[1];
    const int*   s1 = (const int*)d_in[2];
    const int*   e1 = (const int*)d_in[3];
    const int*   s2 = (const int*)d_in[4];
    const int*   e2 = (const int*)d_in[5];
    const float* W1 = (const float*)d_in[6];
    const float* b1 = (const float*)d_in[7];
    const float* W2 = (const float*)d_in[8];
    const float* b2 = (const float*)d_in[9];
    const float* W3 = (const float*)d_in[10];
    const float* b3 = (const float*)d_in[11];
    float* out = (float*)d_out;

    feat_kernel<<<dim3(B, 2), 768>>>(x1, x2, s1, e1, s2, e2);
    gemm1_kernel<<<dim3(B / BM, H1 / BN, KS), 128>>>(W1, b1);
    tail_kernel<<<B, H1>>>(W2, b2, W3, b3, out);
}

// round 12
// speedup vs baseline: 1.0615x; 1.0615x over previous
#include <cuda_runtime.h>
#include <cuda_bf16.h>
#include <math.h>
#include <stdint.h>

// Problem constants
#define B   256
#define S   512
#define D   768
#define D4  (D/4)        // 192 float4 per row
#define ROWB (D*4)       // 3072 bytes per row
#define K4D 3072         // 4*D
#define H1  256
#define H2  64
#define L   4

// GEMM1 tiling
#define BM  32
#define BN  64
#define BK  32
#define KS  16
#define KC  (K4D/KS)     // 192 k per split
#define NT  (KC/BK)      // 6 k-tiles per block
#define FS  68           // padded fsh2 row stride (floats), 16B-aligned

// feat smem layout (dynamic)
#define SP_BYTES   (32 * ROWB)            // 98304: up to 32 span rows
#define PART_OFF   SP_BYTES               // float4 part[2][192] = 6144
#define MBAR_OFF   (SP_BYTES + 6144)      // 8 bytes
#define FEAT_SMEM  (MBAR_OFF + 64)

// Scratch (device globals — no allocation allowed)
__device__ float g_f[B * K4D];            // features [256, 3072]  (3 MB)
__device__ float g_h1p[KS * B * H1];      // GEMM1 partials [16, 256, 256] (4 MB)

#define FFMA2(d, a, b) \
    asm("fma.rn.f32x2 %0, %1, %2, %0;" : "+l"(d) : "l"(a), "l"(b))

__device__ __forceinline__ uint32_t smem_u32(const void* p) {
    uint32_t a;
    asm("{ .reg .u64 t; cvta.to.shared.u64 t, %1; cvt.u32.u64 %0, t; }"
        : "=r"(a) : "l"(p));
    return a;
}

// ---------------------------------------------------------------------------
// K1: feature extraction via TMA bulk copy.
// grid (B, 2), 384 threads. The span x[b, lo:hi, :] is CONTIGUOUS in gmem
// (span<=32 rows x 3KB) -> single cp.async.bulk into smem, mbarrier wait,
// conflict-free smem reduction. CLS row via direct float4 LDG.
// ---------------------------------------------------------------------------
__global__ void __launch_bounds__(384) feat_kernel(
    const float* __restrict__ x1, const float* __restrict__ x2,
    const int* __restrict__ s1a, const int* __restrict__ e1a,
    const int* __restrict__ s2a, const int* __restrict__ e2a)
{
    extern __shared__ char smem[];
    float4* rows = reinterpret_cast<float4*>(smem);            // [32][192]
    float4* part = reinterpret_cast<float4*>(smem + PART_OFF); // [2][192]
    const uint32_t mbar = smem_u32(smem + MBAR_OFF);

    const int b   = blockIdx.x;
    const int sel = blockIdx.y;
    const int t   = threadIdx.x;
    const int col = t % D4;      // float4 lane 0..191
    const int rg  = t / D4;      // rowgroup 0..1

    const float* x = sel ? x2 : x1;
    int s = sel ? s2a[b] : s1a[b];
    int e = sel ? e2a[b] : e1a[b];
    e = max(e, s + 1);
    int lo = max(s, 0), hi = min(e, S);
    int cnt = max(hi - lo, 1);
    float inv = 1.0f / (float)cnt;

    const float4* x4 = reinterpret_cast<const float4*>(x);
    float4* f4 = reinterpret_cast<float4*>(g_f);
    const long base = (long)b * S * D4;
    const long frow = (long)b * (K4D / 4) + sel * (2 * D4);

    // issue the span bulk copy ASAP (tid 0)
    if (t == 0) {
        asm volatile("mbarrier.init.shared.b64 [%0], 1;" :: "r"(mbar) : "memory");
        // make init visible to the async proxy before the bulk copy targets it
        asm volatile("fence.proxy.async.shared::cta;" ::: "memory");
        unsigned bytes = (unsigned)cnt * ROWB;
        asm volatile("mbarrier.arrive.expect_tx.shared.b64 _, [%0], %1;"
                     :: "r"(mbar), "r"(bytes) : "memory");
        const char* src = reinterpret_cast<const char*>(x) +
                          ((long)b * S + lo) * (long)ROWB;
        asm volatile(
            "cp.async.bulk.shared::cluster.global.mbarrier::complete_tx::bytes "
            "[%0], [%1], %2, [%3];"
            :: "r"(smem_u32(smem)), "l"(src), "r"(bytes), "r"(mbar) : "memory");
    }

    // CLS copy overlaps the bulk copy (independent LDG)
    if (rg == 0)
        f4[frow + col] = x4[base + col];

    __syncthreads();   // everyone sees the initialized mbarrier

    // wait for the bulk copy (phase 0)
    {
        uint32_t done;
        asm volatile(
            "{\n\t.reg .pred p;\n\t"
            "mbarrier.try_wait.parity.shared.b64 p, [%1], 0;\n\t"
            "selp.b32 %0, 1, 0, p;\n\t}"
            : "=r"(done) : "r"(mbar) : "memory");
        while (!done) {
            asm volatile(
                "{\n\t.reg .pred p;\n\t"
                "mbarrier.try_wait.parity.shared.b64 p, [%1], 0, 0x989680;\n\t"
                "selp.b32 %0, 1, 0, p;\n\t}"
                : "=r"(done) : "r"(mbar) : "memory");
        }
    }

    // reduce: rowgroup rg sums rows r = rg, rg+2, ... (2 accumulators)
    float4 a0 = make_float4(0.f, 0.f, 0.f, 0.f);
    float4 a1 = make_float4(0.f, 0.f, 0.f, 0.f);
    int r = rg;
    for (; r + 2 < cnt; r += 4) {
        float4 v0 = rows[r * D4 + col];
        float4 v1 = rows[(r + 2) * D4 + col];
        a0.x += v0.x; a0.y += v0.y; a0.z += v0.z; a0.w += v0.w;
        a1.x += v1.x; a1.y += v1.y; a1.z += v1.z; a1.w += v1.w;
    }
    if (r < cnt) {
        float4 v = rows[r * D4 + col];
        a0.x += v.x; a0.y += v.y; a0.z += v.z; a0.w += v.w;
    }
    a0.x += a1.x; a0.y += a1.y; a0.z += a1.z; a0.w += a1.w;
    part[rg * D4 + col] = a0;
    __syncthreads();

    if (t < D4) {
        float4 p0 = part[t], p1 = part[D4 + t];
        float4 o;
        o.x = (p0.x + p1.x) * inv;
        o.y = (p0.y + p1.y) * inv;
        o.z = (p0.z + p1.z) * inv;
        o.w = (p0.w + p1.w) * inv;
        f4[frow + D4 + t] = o;
    }
}

// ---------------------------------------------------------------------------
// K2: GEMM1 split-K16, 32x64 tile, 4x4 micro-tile, packed f32x2 FMA,
// double-buffered smem tiles, one barrier per tile.
// grid (B/BM=8, H1/BN=4, KS=16) = 512 blocks, 128 threads.
// ---------------------------------------------------------------------------
__global__ void __launch_bounds__(128) gemm1_kernel(
    const float* __restrict__ W1, const float* __restrict__ b1)
{
    __shared__ float fsh2[2][BK][FS];     // duplicated f tile x2
    __shared__ float wsh[2][BK][BN];      // w tile x2

    const int m0 = blockIdx.x * BM;
    const int n0 = blockIdx.y * BN;
    const int kz = blockIdx.z;
    const int k0 = kz * KC;

    const int tid = threadIdx.x;
    const int tx = tid % 16;
    const int ty = tid / 16;

    const float4* gf4 = reinterpret_cast<const float4*>(g_f);
    const float4* w4  = reinterpret_cast<const float4*>(W1);

    const int kq   = tid % 8;
    const int mrow = tid / 8;
    const int nq  = tid % 16;
    const int kr0 = tid / 16;

    unsigned long long acc2[4][2];
    #pragma unroll
    for (int r = 0; r < 4; ++r) { acc2[r][0] = 0ull; acc2[r][1] = 0ull; }

    float4 fv[2];
    float4 wv[4];

    // prologue: load + stage tile 0
    #pragma unroll
    for (int i = 0; i < 2; ++i) {
        int m = mrow + i * 16;
        fv[i] = gf4[(long)(m0 + m) * (K4D / 4) + k0 / 4 + kq];
    }
    #pragma unroll
    for (int i = 0; i < 4; ++i) {
        int kr = kr0 + i * 8;
        wv[i] = w4[(long)(k0 + kr) * (H1 / 4) + n0 / 4 + nq];
    }
    #pragma unroll
    for (int i = 0; i < 2; ++i) {
        int m = mrow + i * 16;
        *reinterpret_cast<float2*>(&fsh2[0][kq * 4 + 0][2 * m]) = make_float2(fv[i].x, fv[i].x);
        *reinterpret_cast<float2*>(&fsh2[0][kq * 4 + 1][2 * m]) = make_float2(fv[i].y, fv[i].y);
        *reinterpret_cast<float2*>(&fsh2[0][kq * 4 + 2][2 * m]) = make_float2(fv[i].z, fv[i].z);
        *reinterpret_cast<float2*>(&fsh2[0][kq * 4 + 3][2 * m]) = make_float2(fv[i].w, fv[i].w);
    }
    #pragma unroll
    for (int i = 0; i < 4; ++i) {
        int kr = kr0 + i * 8;
        *reinterpret_cast<float4*>(&wsh[0][kr][nq * 4]) = wv[i];
    }
    __syncthreads();

    #pragma unroll
    for (int kt = 0; kt < NT; ++kt) {
        const int cur = kt & 1;
        const int nxt = cur ^ 1;

        if (kt + 1 < NT) {
            int kb = k0 + (kt + 1) * BK;
            #pragma unroll
            for (int i = 0; i < 2; ++i) {
                int m = mrow + i * 16;
                fv[i] = gf4[(long)(m0 + m) * (K4D / 4) + kb / 4 + kq];
            }
            #pragma unroll
            for (int i = 0; i < 4; ++i) {
                int kr = kr0 + i * 8;
                wv[i] = w4[(long)(kb + kr) * (H1 / 4) + n0 / 4 + nq];
            }
        }

        #pragma unroll
        for (int k = 0; k < BK; ++k) {
            const ulonglong2* fp =
                reinterpret_cast<const ulonglong2*>(&fsh2[cur][k][2 * (ty * 4)]);
            ulonglong2 fa = fp[0];
            ulonglong2 fb = fp[1];
            ulonglong2 wp = *reinterpret_cast<const ulonglong2*>(&wsh[cur][k][tx * 4]);
            FFMA2(acc2[0][0], fa.x, wp.x);  FFMA2(acc2[0][1], fa.x, wp.y);
            FFMA2(acc2[1][0], fa.y, wp.x);  FFMA2(acc2[1][1], fa.y, wp.y);
            FFMA2(acc2[2][0], fb.x, wp.x);  FFMA2(acc2[2][1], fb.x, wp.y);
            FFMA2(acc2[3][0], fb.y, wp.x);  FFMA2(acc2[3][1], fb.y, wp.y);
        }

        if (kt + 1 < NT) {
            #pragma unroll
            for (int i = 0; i < 2; ++i) {
                int m = mrow + i * 16;
                *reinterpret_cast<float2*>(&fsh2[nxt][kq * 4 + 0][2 * m]) = make_float2(fv[i].x, fv[i].x);
                *reinterpret_cast<float2*>(&fsh2[nxt][kq * 4 + 1][2 * m]) = make_float2(fv[i].y, fv[i].y);
                *reinterpret_cast<float2*>(&fsh2[nxt][kq * 4 + 2][2 * m]) = make_float2(fv[i].z, fv[i].z);
                *reinterpret_cast<float2*>(&fsh2[nxt][kq * 4 + 3][2 * m]) = make_float2(fv[i].w, fv[i].w);
            }
            #pragma unroll
            for (int i = 0; i < 4; ++i) {
                int kr = kr0 + i * 8;
                *reinterpret_cast<float4*>(&wsh[nxt][kr][nq * 4]) = wv[i];
            }
            __syncthreads();
        }
    }

    // epilogue: unpack, fold bias into split 0, store partials
    float* outp = g_h1p + (long)kz * (B * H1);
    #pragma unroll
    for (int r = 0; r < 4; ++r) {
        int m = m0 + ty * 4 + r;
        #pragma unroll
        for (int p = 0; p < 2; ++p) {
            int n = n0 + tx * 4 + p * 2;
            float lo = __uint_as_float((unsigned)(acc2[r][p] & 0xffffffffull));
            float hi = __uint_as_float((unsigned)(acc2[r][p] >> 32));
            if (kz == 0) { lo += b1[n]; hi += b1[n + 1]; }
            outp[(long)m * H1 + n]     = lo;
            outp[(long)m * H1 + n + 1] = hi;
        }
    }
}

// ---------------------------------------------------------------------------
// K3: per-batch fused tail.
// ---------------------------------------------------------------------------
__global__ void __launch_bounds__(H1) tail_kernel(
    const float* __restrict__ W2, const float* __restrict__ b2,
    const float* __restrict__ W3, const float* __restrict__ b3,
    float* __restrict__ out)
{
    __shared__ float hsh[H1];
    __shared__ float p2sh[4][H2];
    __shared__ float h2sh[H2];
    __shared__ float lsh[L];

    const int b = blockIdx.x;
    const int t = threadIdx.x;

    {
        float v = 0.f;
        #pragma unroll
        for (int p = 0; p < KS; ++p)
            v += g_h1p[(long)p * (B * H1) + (long)b * H1 + t];
        hsh[t] = fmaxf(v, 0.f);
    }
    __syncthreads();

    {
        const int j  = t % H2;
        const int kg = t / H2;
        float acc = 0.f;
        #pragma unroll 8
        for (int k = kg * 64; k < (kg + 1) * 64; ++k)
            acc = fmaf(hsh[k], W2[k * H2 + j], acc);
        p2sh[kg][j] = acc;
    }
    __syncthreads();

    if (t < H2) {
        float acc = b2[t] + p2sh[0][t] + p2sh[1][t] + p2sh[2][t] + p2sh[3][t];
        h2sh[t] = fmaxf(acc, 0.f);
    }
    __syncthreads();

    if (t < L) {
        float acc = b3[t];
        #pragma unroll
        for (int k = 0; k < H2; ++k)
            acc = fmaf(h2sh[k], W3[k * L + t], acc);
        lsh[t] = acc;
    }
    __syncthreads();

    if (t < L) {
        float mx = lsh[0];
        #pragma unroll
        for (int l = 1; l < L; ++l) mx = fmaxf(mx, lsh[l]);
        float s = 0.f;
        #pragma unroll
        for (int l = 0; l < L; ++l) s += expf(lsh[l] - mx);
        out[b * L + t] = expf(lsh[t] - mx) / s;
    }
}

// ---------------------------------------------------------------------------
extern "C" void kernel_launch(void* const* d_in, const int* in_sizes, int n_in,
                              void* d_out, int out_size)
{
    const float* x1 = (const float*)d_in[0];
    const float* x2 = (const float*)d_in[1];
    const int*   s1 = (const int*)d_in[2];
    const int*   e1 = (const int*)d_in[3];
    const int*   s2 = (const int*)d_in[4];
    const int*   e2 = (const int*)d_in[5];
    const float* W1 = (const float*)d_in[6];
    const float* b1 = (const float*)d_in[7];
    const float* W2 = (const float*)d_in[8];
    const float* b2 = (const float*)d_in[9];
    const float* W3 = (const float*)d_in[10];
    const float* b3 = (const float*)d_in[11];
    float* out = (float*)d_out;

    cudaFuncSetAttribute(feat_kernel,
                         cudaFuncAttributeMaxDynamicSharedMemorySize, FEAT_SMEM);

    feat_kernel<<<dim3(B, 2), 384, FEAT_SMEM>>>(x1, x2, s1, e1, s2, e2);
    gemm1_kernel<<<dim3(B / BM, H1 / BN, KS), 128>>>(W1, b1);
    tail_kernel<<<B, H1>>>(W2, b2, W3, b3, out);
}